// round 10
// baseline (speedup 1.0000x reference)
#include <cuda_runtime.h>
#include <cstdint>

// QORNN: B=256, T=1024, I=64, H=256, O=16
// Exact integer reformulation (bit-exact vs reference; rel_err 0.0 R2-R8):
//   x_q  = clip(rint(x*128), -128, 127)          int8, scale 1/128
//   W*_q = clip(rint(W*8), -8, 7)                int4-valued int8, scale 1/8
//   z    = (xq@Wiq + hq@Wrq) / 1024              int32 accum, exact in fp32 grid
//   m = relu(|z|+b); h_q = clip(rint(sign(z)*m*128), -128, 127)
// R9: k-split design. Grid 128, one 512-thread CTA per SM, 2 batch rows/CTA.
// Thread (u = tid>>1, half = tid&1) computes the k-half dot for unit u on BOTH
// rows; halves combine via one shfl_xor(1); even/odd lanes do row0/row1
// epilogues. Weights stored ONCE per SM (40 regs/thread, was 80) -> deep LDS
// batching under the 128-reg cap. k-halves interleaved by 16B block so each
// warp LDS hits two adjacent blocks (conflict-free broadcast).

#define TT 1024
#define NB 256
#define HH 256
#define NI 64
#define NO 16

#define NWR (HH * 64)            // 16384 packed words
#define NWI (HH * 16)            // 4096
#define NWO (NO * 64)            // 1024
#define NPACK (NWR + NWI + NWO)  // 21504 = 84 * 256

__device__ uint32_t g_WiP[NWI];
__device__ uint32_t g_WrP[NWR];
__device__ uint32_t g_WoP[NWO];

__device__ __forceinline__ int clampi(int v, int lo, int hi) {
    return v < lo ? lo : (v > hi ? hi : v);
}

__device__ __forceinline__ uint32_t pack4(const float* p) {
    uint32_t w = 0;
#pragma unroll
    for (int j = 0; j < 4; j++) {
        int q = clampi((int)rintf(p[j] * 8.0f), -8, 7);
        w |= ((uint32_t)(uint8_t)(int8_t)q) << (8 * j);
    }
    return w;
}

// One packed word per thread; 84 CTAs x 256 threads = 21504 words.
__global__ __launch_bounds__(256)
void prep_kernel(const float* __restrict__ Wi,
                 const float* __restrict__ Wr,
                 const float* __restrict__ Wo) {
    int i = blockIdx.x * 256 + threadIdx.x;
    if (i < NWR) {
        int row = i >> 6, kw = i & 63;
        g_WrP[i] = pack4(Wr + row * HH + kw * 4);
    } else if (i < NWR + NWI) {
        int j = i - NWR;
        int row = j >> 4, kw = j & 15;
        g_WiP[j] = pack4(Wi + row * NI + kw * 4);
    } else if (i < NPACK) {
        int j = i - NWR - NWI;
        int row = j >> 6, kw = j & 63;
        g_WoP[j] = pack4(Wo + row * HH + kw * 4);
    }
}

// int8 quantize, round-half-even via magic add. v*128 is a power-of-two scale
// (exact), so the FMA's single rounding == reference's mul-then-round.
__device__ __forceinline__ int quant8(float v) {
    float tm = fmaf(v, 128.0f, 12582912.0f);        // 2^23 + 2^22
    int q = __float_as_int(tm) - 0x4B400000;        // rint(v*128), half-even
    return max(-128, min(127, q));
}

// modrelu + activation quantization, no I2F / no predicate selects.
// g = RN(az/8 + 128b) = 128*RN(|z|/1024 + b) (power-of-2 scaling commutes);
// relu and *128 commute; magic round = rint half-even; sign/clamp exact.
__device__ __forceinline__ int modrelu_q(int z, float bc128) {
    int az = abs(z);                                 // az < 2^19
    float azf = __int_as_float(0x4B000000 + az);     // 2^23 + az, exact
    float t8  = azf * 0.125f;                        // 2^20 + az/8, exact
    float f   = t8 - 1048576.0f;                     // az/8, exact
    float g   = f + bc128;                           // single RN (== ref)
    float m   = fmaxf(g, 0.0f);
    float tm  = m + 12582912.0f;                     // round half-even
    int ni    = __float_as_int(tm) - 0x4B400000;     // ni >= 0
    int s     = z >> 31;                             // -1 if z<0 else 0
    int t2    = min(ni, 127 - s);                    // bound 127 / 128
    int r     = (t2 ^ s) - s;                        // conditional negate
    int nz    = (z | -z) >> 31;                      // -1 iff z != 0
    return r & nz;                                   // sign(0) = 0
}

// Scan: one CTA = 2 batch rows, 512 threads, 1 CTA/SM (grid 128).
__global__ __launch_bounds__(512, 1)
void qornn_kernel(const float* __restrict__ x,
                  const float* __restrict__ b,
                  float* __restrict__ out) {
    __shared__ uint32_t sh_h[2][2][64];   // [buf][row][word] : 256 int8 per row
    __shared__ uint32_t sh_x[2][2][16];   // [buf][row][word] : 64 int8 per row

    const int tid  = threadIdx.x;
    const int u    = tid >> 1;            // hidden unit 0..255
    const int half = tid & 1;             // k-half (interleaved 16B blocks)
    const int r0   = blockIdx.x * 2;

    // Weight halves: uint4 blocks {2j+half} of unit u (interleaved split).
    uint4 wrv[8];
#pragma unroll
    for (int j = 0; j < 8; j++)
        wrv[j] = ((const uint4*)g_WrP)[u * 16 + 2 * j + half];
    uint4 wiv[2];
#pragma unroll
    for (int j = 0; j < 2; j++)
        wiv[j] = ((const uint4*)g_WiP)[u * 4 + 2 * j + half];
    const float bc128 = b[u] * 128.0f;    // exact

    // h0 = 0: 2*2*64 = 256 words
    if (tid < 256) ((uint32_t*)sh_h)[tid] = 0u;

    // x producers: threads 0..127, (row, feat) = (tid>>6, tid&63)
    const int xr = tid >> 6;
    const int xf = tid & 63;
    if (tid < 128) {
        float xv = x[(size_t)(r0 + xr) * (TT * NI) + xf];
        ((int8_t*)sh_x[0][xr])[xf] = (int8_t)quant8(xv);
    }
    __syncthreads();

    // One step: half-dots for unit u on both rows, shfl-combine, epilogue.
#define SCAN_STEP(CUR, TN)                                                    \
    {                                                                         \
        float xv = 0.0f;                                                      \
        if (tid < 128)                                                        \
            xv = x[((size_t)(r0 + xr) * TT + (TN)) * NI + xf];                \
        int a0 = 0, a1 = 0, a2 = 0, a3 = 0;   /* row0 partial */              \
        int c0 = 0, c1 = 0, c2 = 0, c3 = 0;   /* row1 partial */              \
        const uint4* x0 = (const uint4*)sh_x[CUR][0];                         \
        const uint4* x1 = (const uint4*)sh_x[CUR][1];                         \
        _Pragma("unroll")                                                     \
        for (int j = 0; j < 2; j++) {                                         \
            uint4 v0 = x0[2 * j + half], v1 = x1[2 * j + half];               \
            uint4 w = wiv[j];                                                 \
            a0 = __dp4a((int)v0.x, (int)w.x, a0);                             \
            a1 = __dp4a((int)v0.y, (int)w.y, a1);                             \
            a2 = __dp4a((int)v0.z, (int)w.z, a2);                             \
            a3 = __dp4a((int)v0.w, (int)w.w, a3);                             \
            c0 = __dp4a((int)v1.x, (int)w.x, c0);                             \
            c1 = __dp4a((int)v1.y, (int)w.y, c1);                             \
            c2 = __dp4a((int)v1.z, (int)w.z, c2);                             \
            c3 = __dp4a((int)v1.w, (int)w.w, c3);                             \
        }                                                                     \
        const uint4* h0 = (const uint4*)sh_h[CUR][0];                         \
        const uint4* h1 = (const uint4*)sh_h[CUR][1];                         \
        _Pragma("unroll")                                                     \
        for (int j = 0; j < 8; j++) {                                         \
            uint4 v0 = h0[2 * j + half], v1 = h1[2 * j + half];               \
            uint4 w = wrv[j];                                                 \
            a0 = __dp4a((int)v0.x, (int)w.x, a0);                             \
            a1 = __dp4a((int)v0.y, (int)w.y, a1);                             \
            a2 = __dp4a((int)v0.z, (int)w.z, a2);                             \
            a3 = __dp4a((int)v0.w, (int)w.w, a3);                             \
            c0 = __dp4a((int)v1.x, (int)w.x, c0);                             \
            c1 = __dp4a((int)v1.y, (int)w.y, c1);                             \
            c2 = __dp4a((int)v1.z, (int)w.z, c2);                             \
            c3 = __dp4a((int)v1.w, (int)w.w, c3);                             \
        }                                                                     \
        int A0 = (a0 + a1) + (a2 + a3);   /* row0, own k-half */              \
        int A1 = (c0 + c1) + (c2 + c3);   /* row1, own k-half */              \
        int send = half ? A0 : A1;        /* partner's row */                 \
        int recv = __shfl_xor_sync(0xFFFFFFFFu, send, 1);                     \
        int z = (half ? A1 : A0) + recv;  /* z(row=half, unit=u) */           \
        ((int8_t*)sh_h[CUR ^ 1][half])[u] = (int8_t)modrelu_q(z, bc128);      \
        if (tid < 128)                                                        \
            ((int8_t*)sh_x[CUR ^ 1][xr])[xf] = (int8_t)quant8(xv);            \
        __syncthreads();                                                      \
    }

    for (int t = 0; t < TT; t += 2) {
        SCAN_STEP(0, (t + 1))
        SCAN_STEP(1, (t + 2 < TT ? t + 2 : TT - 1))
    }
#undef SCAN_STEP

    // Output head: h_last in buffer 0 (t=1023: cur=1 wrote nxt=0).
    if (tid < 2 * NO) {
        const int row = tid >> 4;
        const int o = tid & 15;
        const uint32_t* hrow = sh_h[0][row];
        int acc = 0;
#pragma unroll
        for (int kw = 0; kw < 64; kw++)
            acc = __dp4a((int)hrow[kw], (int)g_WoP[o * 64 + kw], acc);
        out[(r0 + row) * NO + o] = (float)acc * (1.0f / 1024.0f);
    }
}

extern "C" void kernel_launch(void* const* d_in, const int* in_sizes, int n_in,
                              void* d_out, int out_size) {
    const float* inputs = (const float*)d_in[0];  // [256,1024,64]
    const float* Wi     = (const float*)d_in[1];  // [256,64]
    const float* Wr     = (const float*)d_in[2];  // [256,256]
    const float* Wo     = (const float*)d_in[3];  // [16,256]
    const float* b      = (const float*)d_in[4];  // [256]
    float* out = (float*)d_out;                   // [256,16]

    prep_kernel<<<(NPACK + 255) / 256, 256>>>(Wi, Wr, Wo);
    qornn_kernel<<<NB / 2, 512>>>(inputs, b, out);
}